// round 4
// baseline (speedup 1.0000x reference)
#include <cuda_runtime.h>

// FIR: out[b,t,c] = sum_{i=0..15} w[i,c] * x[b, t-15+i, c]   (causal, zero-padded)
// x: [B=64, T=2048, C=32] fp32, w: [F=16, C=32] fp32, out: [B, T, C] fp32.
//
// Packed-f32x2 version: each thread owns a channel PAIR (2 adjacent channels)
// and 16 timesteps. All math is fma.rn.f32x2 (sm_10x FFMA2), window kept in a
// 16-slot packed register ring with static indices. Tile+halo staged in SMEM.

#define B_SZ 64
#define T_SZ 2048
#define C_SZ 32
#define F_SZ 16
#define TILE_T 128
#define GRP 16
#define THREADS 128                       // 16 ch-pairs x 8 time-groups

#define HALO (F_SZ - 1)                   // 15
#define SMEM_T (TILE_T + HALO)            // 143
#define SMEM_FLOATS (SMEM_T * C_SZ)       // 4576
#define SMEM_VEC (SMEM_FLOATS / 4)        // 1144 float4
#define ZERO_VEC ((HALO * C_SZ) / 4)      // 120 leading zero-vectors when t0==0

typedef unsigned long long u64;

__device__ __forceinline__ u64 fma2(u64 a, u64 b, u64 c) {
    u64 d;
    asm("fma.rn.f32x2 %0, %1, %2, %3;" : "=l"(d) : "l"(a), "l"(b), "l"(c));
    return d;
}
__device__ __forceinline__ u64 add2(u64 a, u64 b) {
    u64 d;
    asm("add.rn.f32x2 %0, %1, %2;" : "=l"(d) : "l"(a), "l"(b));
    return d;
}

__global__ __launch_bounds__(THREADS, 6)
void fir_kernel(const float* __restrict__ x,
                const float* __restrict__ w,
                float* __restrict__ out) {
    __shared__ float4 tile[SMEM_VEC];

    const int tid = threadIdx.x;
    const int b   = blockIdx.x;
    const int t0  = blockIdx.y * TILE_T;

    // ---- cooperative staging: gmem [t0-15 .. t0+127] x [0..31] -> smem ----
    const long gbase = ((long)b * T_SZ + t0 - HALO) * C_SZ;  // multiple of 16 floats
    const float4* gx = (const float4*)(x + gbase);

    if (t0 != 0) {
#pragma unroll
        for (int k = 0; k < 9; k++) {
            const int v = tid + k * THREADS;
            if (v < SMEM_VEC) tile[v] = gx[v];
        }
    } else {
#pragma unroll
        for (int k = 0; k < 9; k++) {
            const int v = tid + k * THREADS;
            if (v < SMEM_VEC)
                tile[v] = (v < ZERO_VEC) ? make_float4(0.f, 0.f, 0.f, 0.f) : gx[v];
        }
    }

    // ---- packed taps for this thread's channel pair ----
    const int cp = tid & 15;                 // channel pair: channels 2cp, 2cp+1
    u64 wp[F_SZ];
    const u64* wpr = (const u64*)w;          // [16][16] pairs
#pragma unroll
    for (int i = 0; i < F_SZ; i++) wp[i] = wpr[i * 16 + cp];

    __syncthreads();

    // ---- compute: 16 outputs (x2 channels) from a packed register ring ----
    const int u0 = (tid >> 4) * GRP;         // 0,16,...,112
    const u64* smp = (const u64*)tile;       // SMEM as packed pairs, row = 16 pairs

    // win[j & 15] holds smem row (u0 + j); preload j = 0..14
    u64 win[F_SZ];
#pragma unroll
    for (int j = 0; j < HALO; j++)
        win[j] = smp[(u0 + j) * 16 + cp];

    u64* op = (u64*)out + ((long)b * T_SZ + t0 + u0) * 16 + cp;

#pragma unroll
    for (int u = 0; u < GRP; u++) {
        win[(HALO + u) & 15] = smp[(u0 + HALO + u) * 16 + cp];
        u64 acc0 = 0ULL, acc1 = 0ULL;        // packed zeros; 2 chains, depth 8
#pragma unroll
        for (int i = 0; i < F_SZ; i += 2) {
            acc0 = fma2(wp[i],     win[(u + i)     & 15], acc0);
            acc1 = fma2(wp[i + 1], win[(u + i + 1) & 15], acc1);
        }
        op[u * 16] = add2(acc0, acc1);
    }
}

extern "C" void kernel_launch(void* const* d_in, const int* in_sizes, int n_in,
                              void* d_out, int out_size) {
    const float* x = (const float*)d_in[0];   // [64, 2048, 32]
    const float* w = (const float*)d_in[1];   // [16, 32]
    float* out = (float*)d_out;

    dim3 grid(B_SZ, T_SZ / TILE_T);           // (64, 16) = 1024 blocks
    fir_kernel<<<grid, THREADS>>>(x, w, out);
}

// round 5
// speedup vs baseline: 1.0030x; 1.0030x over previous
#include <cuda_runtime.h>

// FIR: out[b,t,c] = sum_{i=0..15} w[i,c] * x[b, t-15+i, c]   (causal, zero-padded)
// x: [B=64, T=2048, C=32] fp32, w: [F=16, C=32] fp32, out: [B, T, C] fp32.
//
// One thread = one channel PAIR x 16 timesteps (32 outputs). No smem, no
// barriers. 31-entry packed (f32x2) register window, front-batched LDG.64
// (MLP~31, L2-resident input), all math fma.rn.f32x2.

#define B_SZ 64
#define T_SZ 2048
#define C_SZ 32
#define F_SZ 16
#define GRP  16
#define HALO (F_SZ - 1)          // 15
#define NPAIR (C_SZ / 2)         // 16 channel pairs
#define THREADS 256

typedef unsigned long long u64;

__device__ __forceinline__ u64 fma2(u64 a, u64 b, u64 c) {
    u64 d;
    asm("fma.rn.f32x2 %0, %1, %2, %3;" : "=l"(d) : "l"(a), "l"(b), "l"(c));
    return d;
}
__device__ __forceinline__ u64 add2(u64 a, u64 b) {
    u64 d;
    asm("add.rn.f32x2 %0, %1, %2;" : "=l"(d) : "l"(a), "l"(b));
    return d;
}

__global__ __launch_bounds__(THREADS)
void fir_kernel(const float* __restrict__ x,
                const float* __restrict__ w,
                float* __restrict__ out) {
    // global item id -> (b, time-group, channel-pair); consecutive threads
    // share (b,tg) and step cp -> coalesced 128B rows (2 rows per warp).
    const int g  = blockIdx.x * THREADS + threadIdx.x;
    const int cp = g & (NPAIR - 1);
    const int tg = (g >> 4) & (T_SZ / GRP - 1);
    const int b  = g >> 11;
    const int t0 = tg * GRP;

    const u64* xp = (const u64*)x + ((long)b * T_SZ + t0) * NPAIR + cp;

    // taps for this channel pair (L2/L1-hot)
    u64 wp[F_SZ];
    const u64* wpr = (const u64*)w;              // [16][16] pairs
#pragma unroll
    for (int i = 0; i < F_SZ; i++) wp[i] = wpr[i * NPAIR + cp];

    // packed window: win[j] = x-pair at time t0 - 15 + j, j = 0..30
    u64 win[2 * F_SZ - 1];
    if (tg != 0) {
#pragma unroll
        for (int j = 0; j < HALO; j++)
            win[j] = xp[(j - HALO) * NPAIR];
    } else {
#pragma unroll
        for (int j = 0; j < HALO; j++) win[j] = 0ULL;
    }
#pragma unroll
    for (int j = 0; j < GRP; j++)
        win[HALO + j] = xp[j * NPAIR];

    u64* op = (u64*)out + ((long)b * T_SZ + t0) * NPAIR + cp;

#pragma unroll
    for (int u = 0; u < GRP; u++) {
        u64 acc0 = 0ULL, acc1 = 0ULL;            // 2 chains, dep depth 8
#pragma unroll
        for (int i = 0; i < F_SZ; i += 2) {
            acc0 = fma2(wp[i],     win[u + i],     acc0);
            acc1 = fma2(wp[i + 1], win[u + i + 1], acc1);
        }
        op[u * NPAIR] = add2(acc0, acc1);
    }
}

extern "C" void kernel_launch(void* const* d_in, const int* in_sizes, int n_in,
                              void* d_out, int out_size) {
    const float* x = (const float*)d_in[0];   // [64, 2048, 32]
    const float* w = (const float*)d_in[1];   // [16, 32]
    float* out = (float*)d_out;

    const int total = B_SZ * (T_SZ / GRP) * NPAIR;   // 131072 threads
    fir_kernel<<<total / THREADS, THREADS>>>(x, w, out);
}